// round 1
// baseline (speedup 1.0000x reference)
#include <cuda_runtime.h>
#include <math.h>

#define HID   512
#define PH    32
#define BSZ   2048
#define FOURH 2048
#define SW    132   // smem pitch: 16B-aligned rows, reduces STS conflicts

// Scratch (static device globals — no allocation at runtime)
__device__ float g_Wp [FOURH * HID];   // permuted (W_ih + W_hh)
__device__ float g_Wp0[FOURH * HID];   // permuted W_ih (step 0)
__device__ float g_bp [FOURH];         // permuted (b_ih + b_hh)
__device__ float g_h  [2 * BSZ * HID]; // ping-pong h
__device__ float g_c  [BSZ * HID];     // cell state (tile-private, no ping-pong)

// Permutation: gate row r = q*512 + hidx  ->  rp = (hidx/32)*128 + q*32 + (hidx%32)
// so block hb owns contiguous rows [hb*128, hb*128+128): 4 gates x 32 hidden cols.
__global__ void prep_kernel(const float* __restrict__ Wih, const float* __restrict__ Whh,
                            const float* __restrict__ bih, const float* __restrict__ bhh) {
    int idx = blockIdx.x * blockDim.x + threadIdx.x;
    if (idx >= FOURH * HID) return;
    int r = idx / HID, k = idx - r * HID;
    int q = r >> 9, hidx = r & 511;
    int rp = ((hidx >> 5) << 7) + (q << 5) + (hidx & 31);
    float a = Wih[idx];
    g_Wp0[rp * HID + k] = a;
    g_Wp [rp * HID + k] = a + Whh[idx];
    if (k == 0) g_bp[rp] = bih[r] + bhh[r];
}

// One LSTM step: gates = X @ W^T + b, fused activation epilogue.
// Block (mb, hb): rows mb*128..+128, hidden cols hb*32..+32 (x4 gates = 128 gate cols).
__global__ __launch_bounds__(256, 2)
void step_kernel(const float* __restrict__ X, const float* __restrict__ W,
                 float* __restrict__ Hout, int t0) {
    __shared__ float As[2][16][SW];
    __shared__ float Bs[2][16][SW];
    const int tid = threadIdx.x;
    const int tm = tid >> 4, tn = tid & 15;
    const int mb = blockIdx.x, hb = blockIdx.y;
    const float* Abase = X + (mb * 128) * HID;
    const float* Bbase = W + (hb * 128) * HID;

    float acc[8][8];
#pragma unroll
    for (int i = 0; i < 8; i++)
#pragma unroll
        for (int j = 0; j < 8; j++) acc[i][j] = 0.f;

    // prologue: fill buffer 0
#pragma unroll
    for (int i = 0; i < 2; i++) {
        int lin = tid + i * 256;
        int m = lin >> 2, kq = (lin & 3) << 2;
        float4 va = *(const float4*)(Abase + m * HID + kq);
        As[0][kq + 0][m] = va.x; As[0][kq + 1][m] = va.y;
        As[0][kq + 2][m] = va.z; As[0][kq + 3][m] = va.w;
        float4 vb = *(const float4*)(Bbase + m * HID + kq);
        Bs[0][kq + 0][m] = vb.x; Bs[0][kq + 1][m] = vb.y;
        Bs[0][kq + 2][m] = vb.z; Bs[0][kq + 3][m] = vb.w;
    }
    __syncthreads();

    for (int kt = 0; kt < HID; kt += 16) {
        int buf = (kt >> 4) & 1, nbuf = buf ^ 1;
        bool more = (kt + 16) < HID;
        float4 pa[2], pb[2];
        if (more) {
#pragma unroll
            for (int i = 0; i < 2; i++) {
                int lin = tid + i * 256;
                int m = lin >> 2, kq = (lin & 3) << 2;
                pa[i] = *(const float4*)(Abase + m * HID + kt + 16 + kq);
                pb[i] = *(const float4*)(Bbase + m * HID + kt + 16 + kq);
            }
        }
#pragma unroll
        for (int kk = 0; kk < 16; kk++) {
            float a[8], b[8];
            *(float4*)(a)     = *(const float4*)&As[buf][kk][tm * 8];
            *(float4*)(a + 4) = *(const float4*)&As[buf][kk][tm * 8 + 4];
#pragma unroll
            for (int q = 0; q < 4; q++)
                *(float2*)(b + 2 * q) = *(const float2*)&Bs[buf][kk][q * 32 + tn * 2];
#pragma unroll
            for (int i = 0; i < 8; i++)
#pragma unroll
                for (int j = 0; j < 8; j++)
                    acc[i][j] = fmaf(a[i], b[j], acc[i][j]);
        }
        if (more) {
#pragma unroll
            for (int i = 0; i < 2; i++) {
                int lin = tid + i * 256;
                int m = lin >> 2, kq = (lin & 3) << 2;
                As[nbuf][kq + 0][m] = pa[i].x; As[nbuf][kq + 1][m] = pa[i].y;
                As[nbuf][kq + 2][m] = pa[i].z; As[nbuf][kq + 3][m] = pa[i].w;
                Bs[nbuf][kq + 0][m] = pb[i].x; Bs[nbuf][kq + 1][m] = pb[i].y;
                Bs[nbuf][kq + 2][m] = pb[i].z; Bs[nbuf][kq + 3][m] = pb[i].w;
            }
        }
        __syncthreads();
    }

    // Epilogue: j = 2*q + d -> gate q, hidden col hb*32 + tn*2 + d. All gates in-register.
#pragma unroll
    for (int d = 0; d < 2; d++) {
        int col = (hb << 5) + tn * 2 + d;
        float bi = g_bp[hb * 128 +  0 + tn * 2 + d];
        float bf = g_bp[hb * 128 + 32 + tn * 2 + d];
        float bg = g_bp[hb * 128 + 64 + tn * 2 + d];
        float bo = g_bp[hb * 128 + 96 + tn * 2 + d];
#pragma unroll
        for (int i = 0; i < 8; i++) {
            int row = mb * 128 + tm * 8 + i;
            float gi = acc[i][0 + d] + bi;
            float gf = acc[i][2 + d] + bf;
            float gg = acc[i][4 + d] + bg;
            float go = acc[i][6 + d] + bo;
            float cold = t0 ? 0.f : g_c[row * HID + col];
            float si = 1.f / (1.f + __expf(-gi));
            float sf = 1.f / (1.f + __expf(-gf));
            float so = 1.f / (1.f + __expf(-go));
            float cn = fmaf(sf, cold, si * tanhf(gg));
            float hn = so * tanhf(cn);
            g_c[row * HID + col] = cn;
            Hout[row * HID + col] = hn;
        }
    }
}

// y[b][t][:] = h_t[b] @ W_d^T + b_d   (warp per row)
__global__ void out_kernel(const float* __restrict__ H, const float* __restrict__ Wd,
                           const float* __restrict__ bd, float* __restrict__ Y, int t) {
    int warp = threadIdx.x >> 5, lane = threadIdx.x & 31;
    int row = blockIdx.x * 8 + warp;
    const float* h = H + row * HID;
    float s0 = 0.f, s1 = 0.f;
    for (int k = lane; k < HID; k += 32) {
        float hv = h[k];
        s0 = fmaf(hv, Wd[k], s0);
        s1 = fmaf(hv, Wd[HID + k], s1);
    }
#pragma unroll
    for (int o = 16; o > 0; o >>= 1) {
        s0 += __shfl_xor_sync(0xffffffffu, s0, o);
        s1 += __shfl_xor_sync(0xffffffffu, s1, o);
    }
    if (lane == 0) {
        Y[row * (PH * 2) + t * 2 + 0] = s0 + bd[0];
        Y[row * (PH * 2) + t * 2 + 1] = s1 + bd[1];
    }
}

extern "C" void kernel_launch(void* const* d_in, const int* in_sizes, int n_in,
                              void* d_out, int out_size) {
    // metadata order: hist, z, W_ih, W_hh, b_ih, b_hh, W_d, b_d
    const float* z   = (const float*)d_in[1];
    const float* Wih = (const float*)d_in[2];
    const float* Whh = (const float*)d_in[3];
    const float* bih = (const float*)d_in[4];
    const float* bhh = (const float*)d_in[5];
    const float* Wd  = (const float*)d_in[6];
    const float* bd  = (const float*)d_in[7];
    float* Y = (float*)d_out;

    float *hsym = nullptr, *wp = nullptr, *wp0 = nullptr;
    cudaGetSymbolAddress((void**)&hsym, g_h);
    cudaGetSymbolAddress((void**)&wp,   g_Wp);
    cudaGetSymbolAddress((void**)&wp0,  g_Wp0);

    prep_kernel<<<(FOURH * HID + 255) / 256, 256>>>(Wih, Whh, bih, bhh);

    dim3 grid(BSZ / 128, HID / 32);   // 16 x 16
    for (int t = 0; t < PH; t++) {
        const float* X = (t == 0) ? z : (hsym + ((t + 1) & 1) * (size_t)BSZ * HID);
        const float* W = (t == 0) ? wp0 : wp;
        float* Hout = hsym + (t & 1) * (size_t)BSZ * HID;
        step_kernel<<<grid, 256>>>(X, W, Hout, t == 0 ? 1 : 0);
        out_kernel<<<BSZ / 8, 256>>>(Hout, Wd, bd, Y, t);
    }
}

// round 2
// speedup vs baseline: 1.0867x; 1.0867x over previous
#include <cuda_runtime.h>
#include <math.h>

#define HID   512
#define PH    32
#define BSZ   2048
#define FOURH 2048
#define SW    132   // smem pitch: 16B-aligned rows, reduces STS conflicts

// Scratch (static device globals — no allocation at runtime)
__device__ float g_Wp [FOURH * HID];   // permuted (W_ih + W_hh)
__device__ float g_Wp0[FOURH * HID];   // permuted W_ih (step 0)
__device__ float g_bp [FOURH];         // permuted (b_ih + b_hh)
__device__ float g_h  [2 * BSZ * HID]; // ping-pong h
__device__ float g_c  [BSZ * HID];     // cell state (tile-private, no ping-pong)

// Permutation: gate row r = q*512 + hidx  ->  rp = (hidx/32)*128 + q*32 + (hidx%32)
// so block hb owns contiguous rows [hb*128, hb*128+128): 4 gates x 32 hidden cols.
__global__ void prep_kernel(const float* __restrict__ Wih, const float* __restrict__ Whh,
                            const float* __restrict__ bih, const float* __restrict__ bhh) {
    int idx = blockIdx.x * blockDim.x + threadIdx.x;
    if (idx >= FOURH * HID) return;
    int r = idx / HID, k = idx - r * HID;
    int q = r >> 9, hidx = r & 511;
    int rp = ((hidx >> 5) << 7) + (q << 5) + (hidx & 31);
    float a = Wih[idx];
    g_Wp0[rp * HID + k] = a;
    g_Wp [rp * HID + k] = a + Whh[idx];
    if (k == 0) g_bp[rp] = bih[r] + bhh[r];
}

__device__ __forceinline__ unsigned long long pack_dup(float v) {
    unsigned long long r;
    unsigned u = __float_as_uint(v);
    asm("mov.b64 %0, {%1, %1};" : "=l"(r) : "r"(u));
    return r;
}
__device__ __forceinline__ void ffma2(unsigned long long& d, unsigned long long a,
                                      unsigned long long b) {
    asm("fma.rn.f32x2 %0, %1, %2, %3;" : "=l"(d) : "l"(a), "l"(b), "l"(d));
}

// One LSTM step: gates = X @ W^T + b, fused activation epilogue.
// Block (mb, hb): rows mb*128..+128, hidden cols hb*32..+32 (x4 gates = 128 gate cols).
// Inner product uses packed fma.rn.f32x2: acc paired along rows (i), so the A
// fragment is loaded from smem directly as packed 64-bit pairs.
__global__ __launch_bounds__(256, 2)
void step_kernel(const float* __restrict__ X, const float* __restrict__ W,
                 float* __restrict__ Hout, int t0) {
    __shared__ float As[2][16][SW];
    __shared__ float Bs[2][16][SW];
    const int tid = threadIdx.x;
    const int tm = tid >> 4, tn = tid & 15;
    const int mb = blockIdx.x, hb = blockIdx.y;
    const float* Abase = X + (mb * 128) * HID;
    const float* Bbase = W + (hb * 128) * HID;

    // acc2[ip][j]: packed pair for rows (2ip, 2ip+1), gate-col j
    unsigned long long acc2[4][8];
#pragma unroll
    for (int ip = 0; ip < 4; ip++)
#pragma unroll
        for (int j = 0; j < 8; j++) acc2[ip][j] = 0ull;

    // prologue: fill buffer 0
#pragma unroll
    for (int i = 0; i < 2; i++) {
        int lin = tid + i * 256;
        int m = lin >> 2, kq = (lin & 3) << 2;
        float4 va = *(const float4*)(Abase + m * HID + kq);
        As[0][kq + 0][m] = va.x; As[0][kq + 1][m] = va.y;
        As[0][kq + 2][m] = va.z; As[0][kq + 3][m] = va.w;
        float4 vb = *(const float4*)(Bbase + m * HID + kq);
        Bs[0][kq + 0][m] = vb.x; Bs[0][kq + 1][m] = vb.y;
        Bs[0][kq + 2][m] = vb.z; Bs[0][kq + 3][m] = vb.w;
    }
    __syncthreads();

    for (int kt = 0; kt < HID; kt += 16) {
        int buf = (kt >> 4) & 1, nbuf = buf ^ 1;
        bool more = (kt + 16) < HID;
        float4 pa[2], pb[2];
        if (more) {
#pragma unroll
            for (int i = 0; i < 2; i++) {
                int lin = tid + i * 256;
                int m = lin >> 2, kq = (lin & 3) << 2;
                pa[i] = *(const float4*)(Abase + m * HID + kt + 16 + kq);
                pb[i] = *(const float4*)(Bbase + m * HID + kt + 16 + kq);
            }
        }
#pragma unroll
        for (int kk = 0; kk < 16; kk++) {
            // a: 8 consecutive floats -> 4 packed pairs, direct 128-bit smem loads
            unsigned long long a2[4];
            const float* arow = &As[buf][kk][tm * 8];
            ulonglong2 al = *(const ulonglong2*)(arow);
            ulonglong2 ah = *(const ulonglong2*)(arow + 4);
            a2[0] = al.x; a2[1] = al.y; a2[2] = ah.x; a2[3] = ah.y;
            // b: 2 cols per gate, duplicated into (b,b) pairs (ALU pipe)
            unsigned long long bb[8];
#pragma unroll
            for (int q = 0; q < 4; q++) {
                float2 bv = *(const float2*)&Bs[buf][kk][q * 32 + tn * 2];
                bb[2 * q + 0] = pack_dup(bv.x);
                bb[2 * q + 1] = pack_dup(bv.y);
            }
#pragma unroll
            for (int ip = 0; ip < 4; ip++)
#pragma unroll
                for (int j = 0; j < 8; j++)
                    ffma2(acc2[ip][j], a2[ip], bb[j]);
        }
        if (more) {
#pragma unroll
            for (int i = 0; i < 2; i++) {
                int lin = tid + i * 256;
                int m = lin >> 2, kq = (lin & 3) << 2;
                As[nbuf][kq + 0][m] = pa[i].x; As[nbuf][kq + 1][m] = pa[i].y;
                As[nbuf][kq + 2][m] = pa[i].z; As[nbuf][kq + 3][m] = pa[i].w;
                Bs[nbuf][kq + 0][m] = pb[i].x; Bs[nbuf][kq + 1][m] = pb[i].y;
                Bs[nbuf][kq + 2][m] = pb[i].z; Bs[nbuf][kq + 3][m] = pb[i].w;
            }
        }
        __syncthreads();
    }

    // Epilogue: j = 2*q + d -> gate q, hidden col hb*32 + tn*2 + d. All gates in-register.
#pragma unroll
    for (int d = 0; d < 2; d++) {
        int col = (hb << 5) + tn * 2 + d;
        float bi = g_bp[hb * 128 +  0 + tn * 2 + d];
        float bf = g_bp[hb * 128 + 32 + tn * 2 + d];
        float bg = g_bp[hb * 128 + 64 + tn * 2 + d];
        float bo = g_bp[hb * 128 + 96 + tn * 2 + d];
#pragma unroll
        for (int i = 0; i < 8; i++) {
            int ip = i >> 1, hi = i & 1;
            int row = mb * 128 + tm * 8 + i;
            float ai = hi ? __uint_as_float((unsigned)(acc2[ip][0 + d] >> 32))
                          : __uint_as_float((unsigned)(acc2[ip][0 + d]));
            float af = hi ? __uint_as_float((unsigned)(acc2[ip][2 + d] >> 32))
                          : __uint_as_float((unsigned)(acc2[ip][2 + d]));
            float ag = hi ? __uint_as_float((unsigned)(acc2[ip][4 + d] >> 32))
                          : __uint_as_float((unsigned)(acc2[ip][4 + d]));
            float ao = hi ? __uint_as_float((unsigned)(acc2[ip][6 + d] >> 32))
                          : __uint_as_float((unsigned)(acc2[ip][6 + d]));
            float gi = ai + bi;
            float gf = af + bf;
            float gg = ag + bg;
            float go = ao + bo;
            float cold = t0 ? 0.f : g_c[row * HID + col];
            float si = 1.f / (1.f + __expf(-gi));
            float sf = 1.f / (1.f + __expf(-gf));
            float so = 1.f / (1.f + __expf(-go));
            float cn = fmaf(sf, cold, si * tanhf(gg));
            float hn = so * tanhf(cn);
            g_c[row * HID + col] = cn;
            Hout[row * HID + col] = hn;
        }
    }
}

// y[b][t][:] = h_t[b] @ W_d^T + b_d   (warp per row)
__global__ void out_kernel(const float* __restrict__ H, const float* __restrict__ Wd,
                           const float* __restrict__ bd, float* __restrict__ Y, int t) {
    int warp = threadIdx.x >> 5, lane = threadIdx.x & 31;
    int row = blockIdx.x * 8 + warp;
    const float* h = H + row * HID;
    float s0 = 0.f, s1 = 0.f;
    for (int k = lane; k < HID; k += 32) {
        float hv = h[k];
        s0 = fmaf(hv, Wd[k], s0);
        s1 = fmaf(hv, Wd[HID + k], s1);
    }
#pragma unroll
    for (int o = 16; o > 0; o >>= 1) {
        s0 += __shfl_xor_sync(0xffffffffu, s0, o);
        s1 += __shfl_xor_sync(0xffffffffu, s1, o);
    }
    if (lane == 0) {
        Y[row * (PH * 2) + t * 2 + 0] = s0 + bd[0];
        Y[row * (PH * 2) + t * 2 + 1] = s1 + bd[1];
    }
}

extern "C" void kernel_launch(void* const* d_in, const int* in_sizes, int n_in,
                              void* d_out, int out_size) {
    // metadata order: hist, z, W_ih, W_hh, b_ih, b_hh, W_d, b_d
    const float* z   = (const float*)d_in[1];
    const float* Wih = (const float*)d_in[2];
    const float* Whh = (const float*)d_in[3];
    const float* bih = (const float*)d_in[4];
    const float* bhh = (const float*)d_in[5];
    const float* Wd  = (const float*)d_in[6];
    const float* bd  = (const float*)d_in[7];
    float* Y = (float*)d_out;

    float *hsym = nullptr, *wp = nullptr, *wp0 = nullptr;
    cudaGetSymbolAddress((void**)&hsym, g_h);
    cudaGetSymbolAddress((void**)&wp,   g_Wp);
    cudaGetSymbolAddress((void**)&wp0,  g_Wp0);

    prep_kernel<<<(FOURH * HID + 255) / 256, 256>>>(Wih, Whh, bih, bhh);

    dim3 grid(BSZ / 128, HID / 32);   // 16 x 16
    for (int t = 0; t < PH; t++) {
        const float* X = (t == 0) ? z : (hsym + ((t + 1) & 1) * (size_t)BSZ * HID);
        const float* W = (t == 0) ? wp0 : wp;
        float* Hout = hsym + (t & 1) * (size_t)BSZ * HID;
        step_kernel<<<grid, 256>>>(X, W, Hout, t == 0 ? 1 : 0);
        out_kernel<<<BSZ / 8, 256>>>(Hout, Wd, bd, Y, t);
    }
}

// round 4
// speedup vs baseline: 1.8955x; 1.7443x over previous
#include <cuda_runtime.h>
#include <cuda_bf16.h>
#include <math.h>
#include <stdint.h>

#define HID   512
#define PH    32
#define BSZ   2048
#define FOURH 2048
#define SLAB  (BSZ * HID)

#define TM 128
#define TN 256
#define KC 32
#define NCH (HID / KC)   // 16 k-chunks

// stage layout (bytes): A tiles 128x32 bf16 = 8KB, B tiles 256x32 bf16 = 16KB
#define AH_OFF 0
#define AL_OFF 8192
#define BH_OFF 16384
#define BL_OFF 32768
#define STAGE  49152
#define SMEM_DYN (2 * STAGE)

// ---------------- static device scratch ----------------
__device__ __nv_bfloat16 g_xh[(PH + 1) * (size_t)SLAB];
__device__ __nv_bfloat16 g_xl[(PH + 1) * (size_t)SLAB];
__device__ __nv_bfloat16 g_wh [FOURH * HID];
__device__ __nv_bfloat16 g_wl [FOURH * HID];
__device__ __nv_bfloat16 g_wh0[FOURH * HID];
__device__ __nv_bfloat16 g_wl0[FOURH * HID];
__device__ float g_bp[FOURH];
__device__ float g_c[(size_t)BSZ * HID];

// ---------------- helpers ----------------
__device__ __forceinline__ uint32_t smem_u32(const void* p) {
    uint32_t a;
    asm("{ .reg .u64 t; cvta.to.shared.u64 t, %1; cvt.u32.u64 %0, t; }" : "=r"(a) : "l"(p));
    return a;
}
__device__ __forceinline__ uint32_t smoff(int row, int q) {
    return (uint32_t)((row << 6) + (((q) ^ ((row >> 1) & 3)) << 4));
}
__device__ __forceinline__ void cp16(uint32_t dst, const void* src) {
    asm volatile("cp.async.cg.shared.global [%0], [%1], 16;" :: "r"(dst), "l"(src));
}
__device__ __forceinline__ void cp_commit() { asm volatile("cp.async.commit_group;"); }
template <int N>
__device__ __forceinline__ void cp_wait() {
    asm volatile("cp.async.wait_group %0;" :: "n"(N) : "memory");
}
__device__ __forceinline__ void ldsm4(uint32_t* r, uint32_t addr) {
    asm volatile("ldmatrix.sync.aligned.m8n8.x4.shared.b16 {%0,%1,%2,%3}, [%4];"
        : "=r"(r[0]), "=r"(r[1]), "=r"(r[2]), "=r"(r[3]) : "r"(addr));
}
__device__ __forceinline__ void mma16816(float* c, const uint32_t* a, const uint32_t* b) {
    asm volatile(
        "mma.sync.aligned.m16n8k16.row.col.f32.bf16.bf16.f32 "
        "{%0,%1,%2,%3}, {%4,%5,%6,%7}, {%8,%9}, {%0,%1,%2,%3};"
        : "+f"(c[0]), "+f"(c[1]), "+f"(c[2]), "+f"(c[3])
        : "r"(a[0]), "r"(a[1]), "r"(a[2]), "r"(a[3]), "r"(b[0]), "r"(b[1]));
}

// ---------------- prep ----------------
// W row r=q*512+hu -> rp = (hu/64)*256 + q*64 + (hu%64)
__global__ void prep_w(const float* __restrict__ Wih, const float* __restrict__ Whh,
                       const float* __restrict__ bih, const float* __restrict__ bhh) {
    int idx = blockIdx.x * blockDim.x + threadIdx.x;
    if (idx >= FOURH * HID) return;
    int r = idx / HID, k = idx - r * HID;
    int q = r >> 9, hu = r & 511;
    int rp = ((hu >> 6) << 8) + (q << 6) + (hu & 63);
    size_t o = (size_t)rp * HID + k;
    float w0 = Wih[idx];
    float ws = w0 + Whh[idx];
    __nv_bfloat16 h0 = __float2bfloat16(w0);
    g_wh0[o] = h0; g_wl0[o] = __float2bfloat16(w0 - __bfloat162float(h0));
    __nv_bfloat16 hs = __float2bfloat16(ws);
    g_wh[o] = hs;  g_wl[o] = __float2bfloat16(ws - __bfloat162float(hs));
    if (k == 0) g_bp[rp] = bih[r] + bhh[r];
}
__global__ void prep_z(const float* __restrict__ z) {
    int i = blockIdx.x * blockDim.x + threadIdx.x;
    if (i >= BSZ * HID) return;
    float v = z[i];
    __nv_bfloat16 h = __float2bfloat16(v);
    g_xh[i] = h;
    g_xl[i] = __float2bfloat16(v - __bfloat162float(h));
}

// ---------------- per-step: gates GEMM (3-product bf16 split, mma.sync) + LSTM epilogue ----
__device__ __forceinline__ void issue_chunk(char* stage,
                                            const __nv_bfloat16* Ah, const __nv_bfloat16* Al,
                                            const __nv_bfloat16* Bh, const __nv_bfloat16* Bl,
                                            int k0, int tid) {
    uint32_t sb = smem_u32(stage);
    // A tiles: 128 rows x 4 quads x {h,l} = 1024 units; 4 per thread
#pragma unroll
    for (int i = 0; i < 4; ++i) {
        int idx = tid + (i << 8);
        const __nv_bfloat16* src = (idx & 512) ? Al : Ah;
        uint32_t toff = (idx & 512) ? AL_OFF : AH_OFF;
        int w = idx & 511, row = w >> 2, q = w & 3;
        cp16(sb + toff + smoff(row, q), src + (size_t)row * HID + k0 + q * 8);
    }
    // B tiles: 256 rows x 4 quads x {h,l} = 2048 units; 8 per thread
#pragma unroll
    for (int i = 0; i < 8; ++i) {
        int idx = tid + (i << 8);
        const __nv_bfloat16* src = (idx & 1024) ? Bl : Bh;
        uint32_t toff = (idx & 1024) ? BL_OFF : BH_OFF;
        int w = idx & 1023, row = w >> 2, q = w & 3;
        cp16(sb + toff + smoff(row, q), src + (size_t)row * HID + k0 + q * 8);
    }
}

__global__ __launch_bounds__(256, 1)
void step_kernel(const __nv_bfloat16* __restrict__ xh, const __nv_bfloat16* __restrict__ xl,
                 const __nv_bfloat16* __restrict__ wh, const __nv_bfloat16* __restrict__ wl,
                 __nv_bfloat16* __restrict__ xh_o, __nv_bfloat16* __restrict__ xl_o,
                 int t0) {
    extern __shared__ char dyn[];
    __shared__ float bias_sm[TN];
    const int tid = threadIdx.x;
    const int lane = tid & 31, warp = tid >> 5;
    const int wm = warp >> 2, wn = warp & 3;
    const int mb = blockIdx.x, nb = blockIdx.y;

    bias_sm[tid] = g_bp[nb * TN + tid];

    const __nv_bfloat16* Ah = xh + (size_t)(mb * TM) * HID;
    const __nv_bfloat16* Al = xl + (size_t)(mb * TM) * HID;
    const __nv_bfloat16* Bh = wh + (size_t)(nb * TN) * HID;
    const __nv_bfloat16* Bl = wl + (size_t)(nb * TN) * HID;

    float acc[4][8][4];
#pragma unroll
    for (int mi = 0; mi < 4; ++mi)
#pragma unroll
        for (int j = 0; j < 8; ++j)
#pragma unroll
            for (int r = 0; r < 4; ++r) acc[mi][j][r] = 0.f;

    issue_chunk(dyn, Ah, Al, Bh, Bl, 0, tid);
    cp_commit();

    // per-lane fragment address components (within tile, before swizzle)
    const int a_row = wm * 64 + (lane & 7) + ((lane >> 3) & 1) * 8; // + mi*16
    const int a_q0  = (lane >> 4);                                  // + 2*s
    const int b_sel = lane >> 4;                                    // block j or j+1
    const int b_kh  = (lane >> 3) & 1;                              // k-half

    for (int c = 0; c < NCH; ++c) {
        if (c + 1 < NCH)
            issue_chunk(dyn + ((c + 1) & 1) * STAGE, Ah, Al, Bh, Bl, (c + 1) * KC, tid);
        cp_commit();
        if (c + 1 < NCH) cp_wait<1>(); else cp_wait<0>();
        __syncthreads();
        uint32_t st = smem_u32(dyn + (c & 1) * STAGE);
#pragma unroll
        for (int s = 0; s < 2; ++s) {
            uint32_t ah[4][4], al[4][4], bh[8][2], bl[8][2];
#pragma unroll
            for (int mi = 0; mi < 4; ++mi)
                ldsm4(ah[mi], st + AH_OFF + smoff(a_row + mi * 16, a_q0 + 2 * s));
#pragma unroll
            for (int t = 0; t < 4; ++t) {
                int jn = 2 * t + b_sel;
                int row = 8 * (4 * jn + wn) + (lane & 7);
                uint32_t r4[4];
                ldsm4(r4, st + BH_OFF + smoff(row, 2 * s + b_kh));
                bh[2 * t][0] = r4[0]; bh[2 * t][1] = r4[1];
                bh[2 * t + 1][0] = r4[2]; bh[2 * t + 1][1] = r4[3];
            }
#pragma unroll
            for (int mi = 0; mi < 4; ++mi)
#pragma unroll
                for (int j = 0; j < 8; ++j) mma16816(acc[mi][j], ah[mi], bh[j]);
#pragma unroll
            for (int mi = 0; mi < 4; ++mi)
                ldsm4(al[mi], st + AL_OFF + smoff(a_row + mi * 16, a_q0 + 2 * s));
#pragma unroll
            for (int mi = 0; mi < 4; ++mi)
#pragma unroll
                for (int j = 0; j < 8; ++j) mma16816(acc[mi][j], al[mi], bh[j]);
#pragma unroll
            for (int t = 0; t < 4; ++t) {
                int jn = 2 * t + b_sel;
                int row = 8 * (4 * jn + wn) + (lane & 7);
                uint32_t r4[4];
                ldsm4(r4, st + BL_OFF + smoff(row, 2 * s + b_kh));
                bl[2 * t][0] = r4[0]; bl[2 * t][1] = r4[1];
                bl[2 * t + 1][0] = r4[2]; bl[2 * t + 1][1] = r4[3];
            }
#pragma unroll
            for (int mi = 0; mi < 4; ++mi)
#pragma unroll
                for (int j = 0; j < 8; ++j) mma16816(acc[mi][j], ah[mi], bl[j]);
        }
        __syncthreads();
    }

    // ---- fused LSTM epilogue, fully in registers ----
    const int g = lane >> 2, sq = lane & 3;
#pragma unroll
    for (int mi = 0; mi < 4; ++mi) {
#pragma unroll
        for (int jn = 0; jn < 2; ++jn) {
            const float* ci = acc[mi][jn];
            const float* cf = acc[mi][jn + 2];
            const float* cg = acc[mi][jn + 4];
            const float* co = acc[mi][jn + 6];
            int bblk = 4 * jn + wn;
#pragma unroll
            for (int r = 0; r < 4; ++r) {
                int rowl = wm * 64 + mi * 16 + g + (r >> 1) * 8;
                int u = 8 * bblk + 2 * sq + (r & 1);
                int row = mb * TM + rowl;
                int hu = nb * 64 + u;
                float gi = ci[r] + bias_sm[u];
                float gf = cf[r] + bias_sm[64 + u];
                float gg = cg[r] + bias_sm[128 + u];
                float go = co[r] + bias_sm[192 + u];
                float cold = t0 ? 0.f : g_c[(size_t)row * HID + hu];
                float si = 1.f / (1.f + __expf(-gi));
                float sf = 1.f / (1.f + __expf(-gf));
                float so = 1.f / (1.f + __expf(-go));
                float tg = 2.f / (1.f + __expf(-2.f * gg)) - 1.f;
                float cn = fmaf(sf, cold, si * tg);
                float tc = 2.f / (1.f + __expf(-2.f * cn)) - 1.f;
                float hn = so * tc;
                g_c[(size_t)row * HID + hu] = cn;
                __nv_bfloat16 bhv = __float2bfloat16(hn);
                xh_o[(size_t)row * HID + hu] = bhv;
                xl_o[(size_t)row * HID + hu] = __float2bfloat16(hn - __bfloat162float(bhv));
            }
        }
    }
}

// ---------------- final projection: all 32 steps in one kernel ----------------
__global__ void out_all(const float* __restrict__ Wd, const float* __restrict__ bd,
                        float* __restrict__ Y) {
    int wg = blockIdx.x * 8 + (threadIdx.x >> 5);
    int lane = threadIdx.x & 31;
    int t = wg & (PH - 1), row = wg >> 5;
    const __nv_bfloat16* xh = g_xh + (size_t)(t + 1) * SLAB + (size_t)row * HID;
    const __nv_bfloat16* xl = g_xl + (size_t)(t + 1) * SLAB + (size_t)row * HID;
    float s0 = 0.f, s1 = 0.f;
    for (int k = lane; k < HID; k += 32) {
        float hv = __bfloat162float(xh[k]) + __bfloat162float(xl[k]);
        s0 = fmaf(hv, Wd[k], s0);
        s1 = fmaf(hv, Wd[HID + k], s1);
    }
#pragma unroll
    for (int o = 16; o > 0; o >>= 1) {
        s0 += __shfl_xor_sync(0xffffffffu, s0, o);
        s1 += __shfl_xor_sync(0xffffffffu, s1, o);
    }
    if (lane == 0) {
        Y[(size_t)row * (PH * 2) + t * 2 + 0] = s0 + bd[0];
        Y[(size_t)row * (PH * 2) + t * 2 + 1] = s1 + bd[1];
    }
}

extern "C" void kernel_launch(void* const* d_in, const int* in_sizes, int n_in,
                              void* d_out, int out_size) {
    // metadata order: hist, z, W_ih, W_hh, b_ih, b_hh, W_d, b_d
    const float* z   = (const float*)d_in[1];
    const float* Wih = (const float*)d_in[2];
    const float* Whh = (const float*)d_in[3];
    const float* bih = (const float*)d_in[4];
    const float* bhh = (const float*)d_in[5];
    const float* Wd  = (const float*)d_in[6];
    const float* bd  = (const float*)d_in[7];
    float* Y = (float*)d_out;

    __nv_bfloat16 *xh, *xl, *wh, *wl, *wh0, *wl0;
    cudaGetSymbolAddress((void**)&xh,  g_xh);
    cudaGetSymbolAddress((void**)&xl,  g_xl);
    cudaGetSymbolAddress((void**)&wh,  g_wh);
    cudaGetSymbolAddress((void**)&wl,  g_wl);
    cudaGetSymbolAddress((void**)&wh0, g_wh0);
    cudaGetSymbolAddress((void**)&wl0, g_wl0);

    cudaFuncSetAttribute(step_kernel, cudaFuncAttributeMaxDynamicSharedMemorySize, SMEM_DYN);

    prep_w<<<(FOURH * HID + 255) / 256, 256>>>(Wih, Whh, bih, bhh);
    prep_z<<<(BSZ * HID + 255) / 256, 256>>>(z);

    dim3 grid(BSZ / TM, FOURH / TN);   // 16 x 8 = 128 CTAs
    for (int t = 0; t < PH; ++t) {
        const __nv_bfloat16* xhi = xh + (size_t)t * SLAB;
        const __nv_bfloat16* xli = xl + (size_t)t * SLAB;
        __nv_bfloat16* xho = xh + (size_t)(t + 1) * SLAB;
        __nv_bfloat16* xlo = xl + (size_t)(t + 1) * SLAB;
        step_kernel<<<grid, 256, SMEM_DYN>>>(xhi, xli,
                                             t == 0 ? wh0 : wh, t == 0 ? wl0 : wl,
                                             xho, xlo, t == 0 ? 1 : 0);
    }
    out_all<<<BSZ * PH / 8, 256>>>(Wd, bd, Y);
}